// round 7
// baseline (speedup 1.0000x reference)
#include <cuda_runtime.h>
#include <math.h>

#define BATCH 2048
#define TT    2048
#define HH    25
#define NPAIR 13

typedef unsigned long long u64;

// Packed f32x2 ops (Blackwell, PTX-only). Two fp32 FMAs/MULs per instruction.
__device__ __forceinline__ u64 ffma2(u64 a, u64 b, u64 c) {
    u64 d; asm("fma.rn.f32x2 %0, %1, %2, %3;" : "=l"(d) : "l"(a), "l"(b), "l"(c)); return d;
}
__device__ __forceinline__ u64 fmul2(u64 a, u64 b) {
    u64 d; asm("mul.rn.f32x2 %0, %1, %2;" : "=l"(d) : "l"(a), "l"(b)); return d;
}
__device__ __forceinline__ u64 pk2(float lo, float hi) {
    u64 r; asm("mov.b64 %0, {%1, %2};" : "=l"(r) : "f"(lo), "f"(hi)); return r;
}
// Zero-instruction unpack: pair halves read directly from the register pair.
__device__ __forceinline__ float lo2(u64 a) { return __uint_as_float((unsigned)a); }
__device__ __forceinline__ float hi2(u64 a) { return __uint_as_float((unsigned)(a >> 32)); }

__device__ __forceinline__ float ex2a(float x) { float r; asm("ex2.approx.f32 %0, %1;" : "=f"(r) : "f"(x)); return r; }
__device__ __forceinline__ float rcpa(float x) { float r; asm("rcp.approx.f32 %0, %1;" : "=f"(r) : "f"(x)); return r; }

__device__ __forceinline__ u64 lds64(unsigned addr) {
    u64 r; asm volatile("ld.shared.b64 %0, [%1];" : "=l"(r) : "r"(addr) : "memory"); return r;
}
__device__ __forceinline__ void sts32(unsigned addr, float v) {
    asm volatile("st.shared.f32 [%0], %1;" :: "r"(addr), "f"(v) : "memory");
}

#define LOG2E 1.44269504088896340736f
__device__ __forceinline__ float sig_f(float x)  { return rcpa(1.0f + ex2a(-LOG2E * x)); }
__device__ __forceinline__ float tanh_f(float x) { return fmaf(2.0f, rcpa(1.0f + ex2a(-2.0f * LOG2E * x)), -1.0f); }

// One warp per sequence; lane j owns hidden unit j. Weights: 13 packed f32x2
// pairs per gate in registers; pair 12 hi slot = gate bias, fed by a constant
// 1.0 parked in shared slot 25 of both ping-pong buffers. Per step:
// 13 broadcast LDS.64 + 48 FFMA2 + 4 FMUL2, activations, STS.32, syncwarp.
// Dense head (prev h) overlaps the matvec; y stored one step delayed.
// Issue-slot diet: literal ping-pong addresses via a 2-step unrolled body
// (no SELs), precomputed STS addresses, shift/cast pair unpack (no MOV64s),
// mul2-seeded accumulators (no zero-init), float2 x stream with one predicate
// per 2-step block, bump-pointer output store.
__global__ void __launch_bounds__(64, 7)
lstm_fused(const float* __restrict__ x,        // [B, T, 1]
           const float* __restrict__ w_ih,     // [4H, 1]
           const float* __restrict__ w_hh,     // [4H, H]
           const float* __restrict__ b_ih,     // [4H]
           const float* __restrict__ b_hh,     // [4H]
           const float* __restrict__ w_dense,  // [1, H]
           const float* __restrict__ b_dense,  // [1]
           float* __restrict__ out)            // [B, T, 1]
{
    __shared__ __align__(16) float hsh[2][2][32];   // [buf][warp][slot]

    const int w    = (int)(threadIdx.x >> 5);
    const int lane = (int)(threadIdx.x & 31u);
    const int gwarp = blockIdx.x * 2 + w;
    const int j = (lane < HH) ? lane : (HH - 1);

    // ---- per-lane weights: 4 gates x 13 packed pairs ----
    u64 W[4][NPAIR];
#pragma unroll
    for (int g = 0; g < 4; g++) {
        const float* row = w_hh + (g * HH + j) * HH;
#pragma unroll
        for (int p = 0; p < NPAIR - 1; p++)
            W[g][p] = pk2(row[2 * p], row[2 * p + 1]);
        W[g][NPAIR - 1] = pk2(row[24], b_ih[g * HH + j] + b_hh[g * HH + j]);
    }
    const float ui = w_ih[0 * HH + j], uf = w_ih[1 * HH + j];
    const float ug = w_ih[2 * HH + j], uo = w_ih[3 * HH + j];
    const float wd = (lane < HH) ? w_dense[lane] : 0.0f;
    const float bd = b_dense[0];

    const float2* xp   = reinterpret_cast<const float2*>(x + (size_t)gwarp * TT);
    float*        op   = out + (size_t)gwarp * TT;

    const unsigned a0 = (unsigned)__cvta_generic_to_shared(&hsh[0][w][0]);
    const unsigned a1 = (unsigned)__cvta_generic_to_shared(&hsh[1][w][0]);
    const unsigned sa0 = a0 + 4u * (unsigned)lane;   // per-lane store addrs
    const unsigned sa1 = a1 + 4u * (unsigned)lane;

    // init both buffers: h=0 everywhere, slot 25 = 1.0 (permanent bias feed)
    {
        const float v = (lane == HH) ? 1.0f : 0.0f;
        hsh[0][w][lane] = v;
        hsh[1][w][lane] = v;
    }
    __syncwarp();

    float h = 0.0f, c = 0.0f;
    float2 xq = xp[0];
    bool first = true;

    // One LSTM step. RA is the literal shared read address (no select), SW the
    // literal per-lane store address, XV the input scalar.
#define STEP(RA, SW, XV)                                                      \
    {                                                                         \
        /* dense head for PREVIOUS h, overlapped with the matvec */           \
        float pr = h * wd;                                                    \
        pr += __shfl_xor_sync(0xffffffffu, pr, 16);                           \
        pr += __shfl_xor_sync(0xffffffffu, pr, 8);                            \
        pr += __shfl_xor_sync(0xffffffffu, pr, 4);                            \
        pr += __shfl_xor_sync(0xffffffffu, pr, 2);                            \
        pr += __shfl_xor_sync(0xffffffffu, pr, 1);                            \
        u64 h0 = lds64(RA);                                                   \
        u64 ai = fmul2(h0, W[0][0]);                                          \
        u64 af = fmul2(h0, W[1][0]);                                          \
        u64 ag = fmul2(h0, W[2][0]);                                          \
        u64 ao = fmul2(h0, W[3][0]);                                          \
        _Pragma("unroll")                                                     \
        for (int p = 1; p < NPAIR; p++) {                                     \
            const u64 hpv = lds64((RA) + 8u * p);                             \
            ai = ffma2(hpv, W[0][p], ai);                                     \
            af = ffma2(hpv, W[1][p], af);                                     \
            ag = ffma2(hpv, W[2][p], ag);                                     \
            ao = ffma2(hpv, W[3][p], ao);                                     \
        }                                                                     \
        const float pi = fmaf((XV), ui, lo2(ai) + hi2(ai));                   \
        const float pf = fmaf((XV), uf, lo2(af) + hi2(af));                   \
        const float pg = fmaf((XV), ug, lo2(ag) + hi2(ag));                   \
        const float po = fmaf((XV), uo, lo2(ao) + hi2(ao));                   \
        const float gi = sig_f(pi);                                           \
        const float gf = sig_f(pf);                                           \
        const float gg = tanh_f(pg);                                          \
        const float go = sig_f(po);                                           \
        c = fmaf(gf, c, gi * gg);                                             \
        h = go * tanh_f(c);                                                   \
        if (lane < HH) sts32((SW), h);                                        \
        if (lane == 0 && !first) *op++ = pr + bd;  /* y[t-1], delayed */      \
        first = false;                                                        \
        __syncwarp();                                                         \
    }

#pragma unroll 1
    for (int tb = 0; tb < TT / 2; tb++) {
        // prefetch next float2 block (one predicate per 2 steps)
        float2 xn = xp[(tb + 1 < TT / 2) ? tb + 1 : tb];
        STEP(a0, sa1, xq.x)    // even step: read buf0, write buf1
        STEP(a1, sa0, xq.y)    // odd step:  read buf1, write buf0
        xq = xn;
    }
#undef STEP

    // final output element y[T-1]
    float pr = h * wd;
    pr += __shfl_xor_sync(0xffffffffu, pr, 16);
    pr += __shfl_xor_sync(0xffffffffu, pr, 8);
    pr += __shfl_xor_sync(0xffffffffu, pr, 4);
    pr += __shfl_xor_sync(0xffffffffu, pr, 2);
    pr += __shfl_xor_sync(0xffffffffu, pr, 1);
    if (lane == 0) *op = pr + bd;
}

extern "C" void kernel_launch(void* const* d_in, const int* in_sizes, int n_in,
                              void* d_out, int out_size) {
    const float* x       = (const float*)d_in[0];
    const float* w_ih    = (const float*)d_in[1];
    const float* w_hh    = (const float*)d_in[2];
    const float* b_ih    = (const float*)d_in[3];
    const float* b_hh    = (const float*)d_in[4];
    const float* w_dense = (const float*)d_in[5];
    const float* b_dense = (const float*)d_in[6];
    float* out = (float*)d_out;

    // 1024 CTAs x 64 threads = one warp per sequence; 7 CTAs/SM -> 14 warps/SM,
    // single wave across 148 SMs.
    lstm_fused<<<BATCH / 2, 64>>>(x, w_ih, w_hh, b_ih, b_hh,
                                  w_dense, b_dense, out);
}